// round 13
// baseline (speedup 1.0000x reference)
#include <cuda_runtime.h>
#include <math.h>
#include <stdint.h>

#define D_MODEL 1024
#define N_HEADS 16
#define HEAD_DIM 64
#define BATCH 4
#define SEQ 2048
#define MROWS (BATCH * SEQ)          // 8192
#define QKV_N (3 * D_MODEL)          // 3072

// softmax scale folded into K at QKV epilogue: 1/sqrt(64) * log2(e)
#define KSCALE 0.18033688011111793f
#define ONESH2 0x3C003C00u          // f16x2 {1.0, 1.0}

// ---------------- scratch (__device__ globals), all fp16 payloads ----------
__device__ __align__(16) uint32_t g_Q16[BATCH * N_HEADS * SEQ * HEAD_DIM / 2];
__device__ __align__(16) uint32_t g_K16[BATCH * N_HEADS * SEQ * HEAD_DIM / 2];
__device__ __align__(16) uint32_t g_Vh [BATCH * N_HEADS * SEQ * HEAD_DIM / 2];
__device__ __align__(16) uint32_t g_AO16[MROWS * D_MODEL / 2];
__device__ __align__(16) uint32_t g_x16 [MROWS * D_MODEL / 2];
__device__ __align__(16) uint16_t g_w1t16[QKV_N * D_MODEL];    // [N][K] fp16
__device__ __align__(16) uint16_t g_w2t16[D_MODEL * D_MODEL];  // [N][K] fp16

// ---------------- helpers ----------------------------------------------------
__device__ __forceinline__ uint32_t smem_u32(const void* p) {
    uint32_t a;
    asm("{ .reg .u64 t; cvta.to.shared.u64 t, %1; cvt.u32.u64 %0, t; }"
        : "=r"(a) : "l"(p));
    return a;
}
__device__ __forceinline__ float ex2(float x) {
    float r; asm("ex2.approx.f32 %0, %1;" : "=f"(r) : "f"(x)); return r;
}
// packed f16x2 exp2
__device__ __forceinline__ uint32_t h2ex2(uint32_t x) {
    uint32_t r; asm("ex2.approx.f16x2 %0, %1;" : "=r"(r) : "r"(x)); return r;
}
// pack two fp32 -> f16x2 (lo = first arg)
__device__ __forceinline__ uint32_t packh2(float lo, float hi) {
    uint32_t u;
    asm("cvt.rn.f16x2.f32 %0, %1, %2;" : "=r"(u) : "f"(hi), "f"(lo));
    return u;
}
__device__ __forceinline__ uint16_t f2h(float f) {
    uint16_t u; asm("cvt.rn.f16.f32 %0, %1;" : "=h"(u) : "f"(f)); return u;
}
__device__ __forceinline__ void mma_f16(float* d, const uint32_t* a,
                                        uint32_t b0, uint32_t b1) {
    asm volatile(
        "mma.sync.aligned.m16n8k16.row.col.f32.f16.f16.f32 "
        "{%0,%1,%2,%3}, {%4,%5,%6,%7}, {%8,%9}, {%0,%1,%2,%3};\n"
        : "+f"(d[0]), "+f"(d[1]), "+f"(d[2]), "+f"(d[3])
        : "r"(a[0]), "r"(a[1]), "r"(a[2]), "r"(a[3]), "r"(b0), "r"(b1));
}
#define LDSM4(r0, r1, r2, r3, addr) \
    asm volatile("ldmatrix.sync.aligned.m8n8.x4.shared.b16 {%0,%1,%2,%3}, [%4];" \
                 : "=r"(r0), "=r"(r1), "=r"(r2), "=r"(r3) : "r"(addr))
#define LDSM4T(r0, r1, r2, r3, addr) \
    asm volatile("ldmatrix.sync.aligned.m8n8.x4.trans.shared.b16 {%0,%1,%2,%3}, [%4];" \
                 : "=r"(r0), "=r"(r1), "=r"(r2), "=r"(r3) : "r"(addr))
#define CP16(dst, src) \
    asm volatile("cp.async.cg.shared.global [%0], [%1], 16;" :: "r"(dst), "l"(src))
#define CP_COMMIT() asm volatile("cp.async.commit_group;")
#define CP_WAIT(n)  asm volatile("cp.async.wait_group %0;" :: "n"(n))

// ---------------------------------------------------------------------------
// Elementwise fp32 -> fp16x2
// ---------------------------------------------------------------------------
__global__ __launch_bounds__(256)
void cvt_f16_kernel(const float4* __restrict__ src, uint2* __restrict__ dst, int n4)
{
    int i = blockIdx.x * blockDim.x + threadIdx.x;
    if (i >= n4) return;
    float4 v = src[i];
    dst[i] = make_uint2(packh2(v.x, v.y), packh2(v.z, v.w));
}

// Transpose + convert: W[K][N] fp32 -> T[N][K] fp16
__global__ __launch_bounds__(256)
void cvt_transpose_f16(const float* __restrict__ W, uint16_t* __restrict__ T,
                       int K, int N)
{
    __shared__ float tile[32][33];
    const int k0 = blockIdx.y * 32, n0 = blockIdx.x * 32;
    const int tx = threadIdx.x, ty = threadIdx.y;     // 32 x 8
    #pragma unroll
    for (int i = 0; i < 32; i += 8)
        tile[ty + i][tx] = W[(size_t)(k0 + ty + i) * N + n0 + tx];
    __syncthreads();
    #pragma unroll
    for (int i = 0; i < 32; i += 8)
        T[(size_t)(n0 + ty + i) * K + k0 + tx] = f2h(tile[tx][ty + i]);
}

// ---------------------------------------------------------------------------
// FP16 GEMM: 128x128 CTA tile, BK=64, 8 warps (4Mx2N, warp 32x64),
// m16n8k16 mma, 2-stage cp.async double buffer (16 syncs total),
// ldmatrix fragments.  Smem rows 128B data + 16B pad (144B).
// MODE 0: fp32 C.  MODE 1: scatter fp16 Q/K(scaled)/V.
// ---------------------------------------------------------------------------
template <int MODE>
__global__ __launch_bounds__(256, 2)
void hgemm(const uint32_t* __restrict__ A, const uint16_t* __restrict__ Bt16,
           const float* __restrict__ bias, float* __restrict__ C,
           int M, int N, int K)
{
    constexpr int RSTB = 144;                // row stride bytes (64 fp16 + pad)
    constexpr int TBB  = 128 * RSTB;         // 18432 B per operand per stage

    extern __shared__ __align__(16) uint32_t sm[];
    const uint32_t sA = smem_u32(sm);
    const uint32_t sB = sA + 2 * TBB;

    const uint32_t* Bt = (const uint32_t*)Bt16;
    const int Ku = K / 2;

    const int tid  = threadIdx.x;
    const int wid  = tid >> 5;
    const int lane = tid & 31;
    const int qr   = lane >> 2;
    const int qc   = lane & 3;
    const int wm   = wid >> 1;
    const int wn   = wid & 1;

    const int row0 = blockIdx.y * 128;
    const int col0 = blockIdx.x * 128;

    // cp.async: half-row per thread (lr 0..127, 64B each)
    const int lr = tid >> 1, lh = (tid & 1) * 16;     // u32 offset
    const uint32_t* aS0 = A  + (size_t)(row0 + lr) * Ku + lh;
    const uint32_t* bS0 = Bt + (size_t)(col0 + lr) * Ku + lh;
    const uint32_t aD0 = sA + lr * RSTB + lh * 4;
    const uint32_t bD0 = sB + lr * RSTB + lh * 4;

    // ldmatrix lane addressing (byte offsets; b16 elements)
    const int a_row = (lane & 7) + ((lane >> 3) & 1) * 8;   // + wm*32 + mt*16
    const int a_ko  = (lane >> 4) * 16;
    const int b_row = (lane & 7) + (lane >> 4) * 8;          // + wn*64 + np*16
    const int b_ko  = ((lane >> 3) & 1) * 16;

    float acc[2][8][4] = {};
    const int NK = K / 64;

    auto load_tile = [&](int kt, int s) {
        const uint32_t* as = aS0 + kt * 32;
        const uint32_t* bs = bS0 + kt * 32;
        const uint32_t ad = aD0 + s * TBB;
        const uint32_t bd = bD0 + s * TBB;
        #pragma unroll
        for (int i = 0; i < 4; i++) {
            CP16(ad + i * 16, as + i * 4);
            CP16(bd + i * 16, bs + i * 4);
        }
        CP_COMMIT();
    };

    load_tile(0, 0);

    for (int kt = 0; kt < NK; kt++) {
        CP_WAIT(0);
        __syncthreads();
        if (kt + 1 < NK) load_tile(kt + 1, (kt + 1) & 1);

        const int cur = kt & 1;
        const uint32_t ab = sA + cur * TBB;
        const uint32_t bb = sB + cur * TBB;
        #pragma unroll
        for (int ks = 0; ks < 4; ks++) {       // four k16 steps per k64 tile
            uint32_t af[2][4], bf[8][2];
            #pragma unroll
            for (int mt = 0; mt < 2; mt++)
                LDSM4(af[mt][0], af[mt][1], af[mt][2], af[mt][3],
                      ab + (wm * 32 + mt * 16 + a_row) * RSTB + a_ko + ks * 32);
            #pragma unroll
            for (int np = 0; np < 4; np++)
                LDSM4(bf[np * 2][0], bf[np * 2][1], bf[np * 2 + 1][0], bf[np * 2 + 1][1],
                      bb + (wn * 64 + np * 16 + b_row) * RSTB + b_ko + ks * 32);
            #pragma unroll
            for (int mt = 0; mt < 2; mt++)
                #pragma unroll
                for (int nt = 0; nt < 8; nt++)
                    mma_f16(acc[mt][nt], af[mt], bf[nt][0], bf[nt][1]);
        }
    }

    // epilogue
    #pragma unroll
    for (int mt = 0; mt < 2; mt++) {
        const int r = row0 + wm * 32 + mt * 16 + qr;
        #pragma unroll
        for (int nt = 0; nt < 8; nt++) {
            const int c = col0 + wn * 64 + nt * 8 + 2 * qc;
            const float bz0 = bias[c], bz1 = bias[c + 1];
            const float v00 = acc[mt][nt][0] + bz0;
            const float v01 = acc[mt][nt][1] + bz1;
            const float v10 = acc[mt][nt][2] + bz0;
            const float v11 = acc[mt][nt][3] + bz1;
            if (MODE == 0) {
                *(float2*)&C[(size_t)r * N + c]       = make_float2(v00, v01);
                *(float2*)&C[(size_t)(r + 8) * N + c] = make_float2(v10, v11);
            } else {
                const int sec = c >> 10, cc = c & 1023;
                const int h = cc >> 6, d = cc & 63;
                const int b = r >> 11, t = r & 2047;
                const float sc = (sec == 1) ? KSCALE : 1.0f;
                uint32_t* dst = (sec == 0 ? g_Q16 : sec == 1 ? g_K16 : g_Vh);
                const size_t off = (((size_t)(b * N_HEADS + h) * SEQ + t) * HEAD_DIM + d) >> 1;
                dst[off]       = packh2(v00 * sc, v01 * sc);
                dst[off + 256] = packh2(v10 * sc, v11 * sc);   // +8 rows
            }
        }
    }
}

// ---------------------------------------------------------------------------
// FP16 flash attention, causal.  128 q rows, 4 warps x 32 rows, 3 CTAs/SM.
// S = QK^T fp16 k16.  P in registers via packed ex2.f16x2.  Row-sum l via
// tensor core (all-ones B).  Per-warp causal tile skip.  Double-buffered.
// ---------------------------------------------------------------------------
__global__ __launch_bounds__(128, 3)
void flash_tc_kernel()
{
    constexpr int ROWB = 144;            // row stride bytes (72 fp16)
    constexpr int TILB = 64 * ROWB;      // 9216 B per buffer

    extern __shared__ __align__(16) char smemc[];
    const uint32_t sK = smem_u32(smemc);
    const uint32_t sV = sK + 2 * TILB;

    const int bh   = blockIdx.y;
    const int qx   = gridDim.x - 1 - blockIdx.x;       // heavy tiles first
    const int tid  = threadIdx.x;
    const int wid  = tid >> 5;                         // 0..3
    const int lane = tid & 31;
    const int qr   = lane >> 2;
    const int qc   = lane & 3;

    const uint32_t* Qb = g_Q16 + (size_t)bh * SEQ * (HEAD_DIM / 2);
    const uint32_t* Kb = g_K16 + (size_t)bh * SEQ * (HEAD_DIM / 2);
    const uint32_t* Vb = g_Vh  + (size_t)bh * SEQ * (HEAD_DIM / 2);

    const int rowbase = qx * 128 + wid * 32;
    const int lastTile    = (rowbase + 31) >> 6;       // last tile this warp needs
    const int firstMasked = (rowbase + 1) >> 6;        // first tile needing mask

    // persistent Q fragments: 2 m16 sub-tiles x 4 k16 chunks
    uint32_t qf[2][4][4];
    #pragma unroll
    for (int mt = 0; mt < 2; mt++) {
        const uint32_t* r0 = Qb + (size_t)(rowbase + mt * 16 + qr) * (HEAD_DIM / 2);
        const uint32_t* r1 = r0 + 8 * (HEAD_DIM / 2);
        #pragma unroll
        for (int kc = 0; kc < 4; kc++) {
            qf[mt][kc][0] = r0[kc * 8 + qc];
            qf[mt][kc][1] = r1[kc * 8 + qc];
            qf[mt][kc][2] = r0[kc * 8 + qc + 4];
            qf[mt][kc][3] = r1[kc * 8 + qc + 4];
        }
    }

    float oacc[2][8][4] = {};
    float lacc[2][4] = {};
    float mm[2][2] = {{-1e30f, -1e30f}, {-1e30f, -1e30f}};

    const int nkt = 2 * (qx + 1);

    // loader coords
    const int ldrow  = tid >> 1;
    const int ldhalf = tid & 1;

    // ldmatrix lane addressing
    const int kb_row = (lane & 7) + (lane >> 4) * 8;        // K B-frags (+np*16)
    const int kb_ko  = ((lane >> 3) & 1) * 16;
    const int v_key  = (lane & 7) + ((lane >> 3) & 1) * 8;  // V trans frags
    const int v_d    = ((lane >> 4) & 1) * 8;

    auto load_tile = [&](int kt, int buf) {
        const uint32_t kD = sK + buf * TILB + ldrow * ROWB + ldhalf * 64;
        const uint32_t vD = sV + buf * TILB + ldrow * ROWB + ldhalf * 64;
        const uint32_t* kS = Kb + (size_t)(kt * 64 + ldrow) * 32 + ldhalf * 16;
        const uint32_t* vS = Vb + (size_t)(kt * 64 + ldrow) * 32 + ldhalf * 16;
        #pragma unroll
        for (int i = 0; i < 4; i++) {
            CP16(kD + i * 16, kS + i * 4);
            CP16(vD + i * 16, vS + i * 4);
        }
        CP_COMMIT();
    };

    load_tile(0, 0);

    for (int kt = 0; kt < nkt; kt++) {
        const int cur = kt & 1;
        const int kb = kt * 64;

        CP_WAIT(0);
        __syncthreads();
        if (kt + 1 < nkt) load_tile(kt + 1, cur ^ 1);

        if (kt > lastTile) continue;           // warp-uniform causal skip

        const uint32_t kbuf = sK + cur * TILB;
        const uint32_t vbuf = sV + cur * TILB;

        // ---- S = Q K^T (fp16 k16) ----
        float sa[2][8][4];
        #pragma unroll
        for (int mt = 0; mt < 2; mt++)
            #pragma unroll
            for (int nt = 0; nt < 8; nt++) {
                sa[mt][nt][0] = 0.f; sa[mt][nt][1] = 0.f;
                sa[mt][nt][2] = 0.f; sa[mt][nt][3] = 0.f;
            }
        #pragma unroll
        for (int kc = 0; kc < 4; kc++) {
            #pragma unroll
            for (int np = 0; np < 4; np++) {
                uint32_t r0, r1, r2, r3;
                LDSM4(r0, r1, r2, r3,
                      kbuf + (np * 16 + kb_row) * ROWB + kb_ko + kc * 32);
                mma_f16(sa[0][np * 2],     qf[0][kc], r0, r1);
                mma_f16(sa[0][np * 2 + 1], qf[0][kc], r2, r3);
                mma_f16(sa[1][np * 2],     qf[1][kc], r0, r1);
                mma_f16(sa[1][np * 2 + 1], qf[1][kc], r2, r3);
            }
        }

        // ---- mask + online softmax; P via packed f16x2 ex2 ----
        uint32_t ph[2][8][2];
        #pragma unroll
        for (int mt = 0; mt < 2; mt++) {
            if (kt >= firstMasked) {
                const int r0g = rowbase + mt * 16 + qr;
                const int r1g = r0g + 8;
                #pragma unroll
                for (int nt = 0; nt < 8; nt++) {
                    const int cg = kb + nt * 8 + 2 * qc;
                    if (cg     > r0g) sa[mt][nt][0] = -1e30f;
                    if (cg + 1 > r0g) sa[mt][nt][1] = -1e30f;
                    if (cg     > r1g) sa[mt][nt][2] = -1e30f;
                    if (cg + 1 > r1g) sa[mt][nt][3] = -1e30f;
                }
            }

            float t0 = -1e30f, t1 = -1e30f;
            #pragma unroll
            for (int nt = 0; nt < 8; nt++) {
                t0 = fmaxf(t0, fmaxf(sa[mt][nt][0], sa[mt][nt][1]));
                t1 = fmaxf(t1, fmaxf(sa[mt][nt][2], sa[mt][nt][3]));
            }
            t0 = fmaxf(t0, __shfl_xor_sync(0xffffffffu, t0, 1));
            t0 = fmaxf(t0, __shfl_xor_sync(0xffffffffu, t0, 2));
            t1 = fmaxf(t1, __shfl_xor_sync(0xffffffffu, t1, 1));
            t1 = fmaxf(t1, __shfl_xor_sync(0xffffffffu, t1, 2));

            const float mn0 = fmaxf(mm[mt][0], t0);
            const float mn1 = fmaxf(mm[mt][1], t1);
            const float c0 = ex2(mm[mt][0] - mn0);
            const float c1 = ex2(mm[mt][1] - mn1);
            lacc[mt][0] *= c0; lacc[mt][1] *= c0;
            lacc[mt][2] *= c1; lacc[mt][3] *= c1;
            #pragma unroll
            for (int nt = 0; nt < 8; nt++) {
                oacc[mt][nt][0] *= c0; oacc[mt][nt][1] *= c0;
                oacc[mt][nt][2] *= c1; oacc[mt][nt][3] *= c1;
            }

            #pragma unroll
            for (int nt = 0; nt < 8; nt++) {
                ph[mt][nt][0] = h2ex2(packh2(sa[mt][nt][0] - mn0,
                                             sa[mt][nt][1] - mn0));
                ph[mt][nt][1] = h2ex2(packh2(sa[mt][nt][2] - mn1,
                                             sa[mt][nt][3] - mn1));
            }
            mm[mt][0] = mn0; mm[mt][1] = mn1;
        }

        // ---- O += P V ; l += P·1  (fp16 k16; P from registers) ----
        #pragma unroll
        for (int j = 0; j < 4; j++) {
            uint32_t pa0[4], pa1[4];
            pa0[0] = ph[0][2 * j][0];     pa0[1] = ph[0][2 * j][1];
            pa0[2] = ph[0][2 * j + 1][0]; pa0[3] = ph[0][2 * j + 1][1];
            pa1[0] = ph[1][2 * j][0];     pa1[1] = ph[1][2 * j][1];
            pa1[2] = ph[1][2 * j + 1][0]; pa1[3] = ph[1][2 * j + 1][1];
            #pragma unroll
            for (int db = 0; db < 4; db++) {
                uint32_t r0, r1, r2, r3;
                const uint32_t addr = vbuf + (j * 16 + v_key) * ROWB
                                    + (db * 16 + v_d) * 2;
                LDSM4T(r0, r1, r2, r3, addr);
                mma_f16(oacc[0][db * 2],     pa0, r0, r1);
                mma_f16(oacc[0][db * 2 + 1], pa0, r2, r3);
                mma_f16(oacc[1][db * 2],     pa1, r0, r1);
                mma_f16(oacc[1][db * 2 + 1], pa1, r2, r3);
            }
            mma_f16(lacc[0], pa0, ONESH2, ONESH2);
            mma_f16(lacc[1], pa1, ONESH2, ONESH2);
        }
    }

    // ---- epilogue: normalize, write fp16 to g_AO16 [B*T][C] ----
    const int b = bh >> 4;
    const int h = bh & 15;
    #pragma unroll
    for (int mt = 0; mt < 2; mt++) {
        const float inv0 = 1.f / lacc[mt][0];
        const float inv1 = 1.f / lacc[mt][2];
        const int t0g = rowbase + mt * 16 + qr;
        uint32_t* o0 = g_AO16 + ((size_t)(b * SEQ + t0g)) * (D_MODEL / 2) + h * 32;
        uint32_t* o1 = o0 + 8 * (D_MODEL / 2);
        #pragma unroll
        for (int nt = 0; nt < 8; nt++) {
            o0[nt * 4 + qc] = packh2(oacc[mt][nt][0] * inv0, oacc[mt][nt][1] * inv0);
            o1[nt * 4 + qc] = packh2(oacc[mt][nt][2] * inv1, oacc[mt][nt][3] * inv1);
        }
    }
}

// ---------------------------------------------------------------------------
extern "C" void kernel_launch(void* const* d_in, const int* in_sizes, int n_in,
                              void* d_out, int out_size)
{
    const float* x     = (const float*)d_in[0];
    const float* W_qkv = (const float*)d_in[1];
    const float* b_qkv = (const float*)d_in[2];
    const float* W_out = (const float*)d_in[3];
    const float* b_out = (const float*)d_in[4];
    float* out = (float*)d_out;

    const int gemm_smem  = 4 * 18432;          // 73728
    const int flash_smem = 4 * 9216;           // 36864
    cudaFuncSetAttribute(hgemm<0>, cudaFuncAttributeMaxDynamicSharedMemorySize, gemm_smem);
    cudaFuncSetAttribute(hgemm<1>, cudaFuncAttributeMaxDynamicSharedMemorySize, gemm_smem);
    cudaFuncSetAttribute(flash_tc_kernel, cudaFuncAttributeMaxDynamicSharedMemorySize, flash_smem);

    uint32_t *x16, *ao;
    uint16_t *w1t, *w2t;
    cudaGetSymbolAddress((void**)&x16, g_x16);
    cudaGetSymbolAddress((void**)&w1t, g_w1t16);
    cudaGetSymbolAddress((void**)&w2t, g_w2t16);
    cudaGetSymbolAddress((void**)&ao,  g_AO16);

    // 0) pre-convert: x -> fp16; weights -> transposed [N][K] fp16
    {
        int n4 = MROWS * D_MODEL / 4;
        cvt_f16_kernel<<<(n4 + 255) / 256, 256>>>((const float4*)x, (uint2*)x16, n4);
        cvt_transpose_f16<<<dim3(QKV_N / 32, D_MODEL / 32), dim3(32, 8)>>>(
            W_qkv, w1t, D_MODEL, QKV_N);
        cvt_transpose_f16<<<dim3(D_MODEL / 32, D_MODEL / 32), dim3(32, 8)>>>(
            W_out, w2t, D_MODEL, D_MODEL);
    }
    // 1) QKV projection -> g_Q16 / g_K16 (scaled) / g_Vh (all fp16)
    {
        dim3 grid(QKV_N / 128, MROWS / 128);    // (24, 64)
        hgemm<1><<<grid, 256, gemm_smem>>>(x16, w1t, b_qkv, nullptr,
                                           MROWS, QKV_N, D_MODEL);
    }
    // 2) causal flash attention -> g_AO16 (fp16)
    {
        dim3 grid(SEQ / 128, BATCH * N_HEADS);  // (16, 64)
        flash_tc_kernel<<<grid, 128, flash_smem>>>();
    }
    // 3) output projection -> d_out (fp32)
    {
        dim3 grid(D_MODEL / 128, MROWS / 128);  // (8, 64)
        hgemm<0><<<grid, 256, gemm_smem>>>(ao, w2t, b_out, out,
                                           MROWS, D_MODEL, D_MODEL);
    }
}

// round 14
// speedup vs baseline: 1.1471x; 1.1471x over previous
#include <cuda_runtime.h>
#include <math.h>
#include <stdint.h>

#define D_MODEL 1024
#define N_HEADS 16
#define HEAD_DIM 64
#define BATCH 4
#define SEQ 2048
#define MROWS (BATCH * SEQ)          // 8192
#define QKV_N (3 * D_MODEL)          // 3072

// softmax scale folded into K at QKV epilogue: 1/sqrt(64) * log2(e)
#define KSCALE 0.18033688011111793f
#define ONESH2 0x3C003C00u          // f16x2 {1.0, 1.0}

// ---------------- scratch (__device__ globals), all fp16 payloads ----------
__device__ __align__(16) uint32_t g_Q16[BATCH * N_HEADS * SEQ * HEAD_DIM / 2];
__device__ __align__(16) uint32_t g_K16[BATCH * N_HEADS * SEQ * HEAD_DIM / 2];
__device__ __align__(16) uint32_t g_Vh [BATCH * N_HEADS * SEQ * HEAD_DIM / 2];
__device__ __align__(16) uint32_t g_AO16[MROWS * D_MODEL / 2];
__device__ __align__(16) uint32_t g_x16 [MROWS * D_MODEL / 2];
__device__ __align__(16) uint16_t g_w1t16[QKV_N * D_MODEL];    // [N][K] fp16
__device__ __align__(16) uint16_t g_w2t16[D_MODEL * D_MODEL];  // [N][K] fp16

// ---------------- helpers ----------------------------------------------------
__device__ __forceinline__ uint32_t smem_u32(const void* p) {
    uint32_t a;
    asm("{ .reg .u64 t; cvta.to.shared.u64 t, %1; cvt.u32.u64 %0, t; }"
        : "=r"(a) : "l"(p));
    return a;
}
__device__ __forceinline__ float ex2(float x) {
    float r; asm("ex2.approx.f32 %0, %1;" : "=f"(r) : "f"(x)); return r;
}
// packed f16x2 exp2
__device__ __forceinline__ uint32_t h2ex2(uint32_t x) {
    uint32_t r; asm("ex2.approx.f16x2 %0, %1;" : "=r"(r) : "r"(x)); return r;
}
// pack two fp32 -> f16x2 (lo = first arg)
__device__ __forceinline__ uint32_t packh2(float lo, float hi) {
    uint32_t u;
    asm("cvt.rn.f16x2.f32 %0, %1, %2;" : "=r"(u) : "f"(hi), "f"(lo));
    return u;
}
__device__ __forceinline__ uint16_t f2h(float f) {
    uint16_t u; asm("cvt.rn.f16.f32 %0, %1;" : "=h"(u) : "f"(f)); return u;
}
__device__ __forceinline__ void mma_f16(float* d, const uint32_t* a,
                                        uint32_t b0, uint32_t b1) {
    asm volatile(
        "mma.sync.aligned.m16n8k16.row.col.f32.f16.f16.f32 "
        "{%0,%1,%2,%3}, {%4,%5,%6,%7}, {%8,%9}, {%0,%1,%2,%3};\n"
        : "+f"(d[0]), "+f"(d[1]), "+f"(d[2]), "+f"(d[3])
        : "r"(a[0]), "r"(a[1]), "r"(a[2]), "r"(a[3]), "r"(b0), "r"(b1));
}
#define LDSM4(r0, r1, r2, r3, addr) \
    asm volatile("ldmatrix.sync.aligned.m8n8.x4.shared.b16 {%0,%1,%2,%3}, [%4];" \
                 : "=r"(r0), "=r"(r1), "=r"(r2), "=r"(r3) : "r"(addr))
#define LDSM4T(r0, r1, r2, r3, addr) \
    asm volatile("ldmatrix.sync.aligned.m8n8.x4.trans.shared.b16 {%0,%1,%2,%3}, [%4];" \
                 : "=r"(r0), "=r"(r1), "=r"(r2), "=r"(r3) : "r"(addr))
#define CP16(dst, src) \
    asm volatile("cp.async.cg.shared.global [%0], [%1], 16;" :: "r"(dst), "l"(src))
#define CP_COMMIT() asm volatile("cp.async.commit_group;")
#define CP_WAIT(n)  asm volatile("cp.async.wait_group %0;" :: "n"(n))

// ---------------------------------------------------------------------------
// Elementwise fp32 -> fp16x2
// ---------------------------------------------------------------------------
__global__ __launch_bounds__(256)
void cvt_f16_kernel(const float4* __restrict__ src, uint2* __restrict__ dst, int n4)
{
    int i = blockIdx.x * blockDim.x + threadIdx.x;
    if (i >= n4) return;
    float4 v = src[i];
    dst[i] = make_uint2(packh2(v.x, v.y), packh2(v.z, v.w));
}

// Transpose + convert: W[K][N] fp32 -> T[N][K] fp16
__global__ __launch_bounds__(256)
void cvt_transpose_f16(const float* __restrict__ W, uint16_t* __restrict__ T,
                       int K, int N)
{
    __shared__ float tile[32][33];
    const int k0 = blockIdx.y * 32, n0 = blockIdx.x * 32;
    const int tx = threadIdx.x, ty = threadIdx.y;     // 32 x 8
    #pragma unroll
    for (int i = 0; i < 32; i += 8)
        tile[ty + i][tx] = W[(size_t)(k0 + ty + i) * N + n0 + tx];
    __syncthreads();
    #pragma unroll
    for (int i = 0; i < 32; i += 8)
        T[(size_t)(n0 + ty + i) * K + k0 + tx] = f2h(tile[tx][ty + i]);
}

// ---------------------------------------------------------------------------
// FP16 GEMM: 128x128 CTA tile, BK=32, 8 warps (4Mx2N, warp 32x64),
// m16n8k16 mma, 4-STAGE cp.async ring (two tiles always in flight),
// ldmatrix fragments.  Smem rows 40 fp16 (80B), conflict-free.
// MODE 0: fp32 C.  MODE 1: scatter fp16 Q/K(scaled)/V.
// ---------------------------------------------------------------------------
template <int MODE>
__global__ __launch_bounds__(256, 2)
void hgemm(const uint32_t* __restrict__ A, const uint16_t* __restrict__ Bt16,
           const float* __restrict__ bias, float* __restrict__ C,
           int M, int N, int K)
{
    constexpr int RSTB = 80;                 // row stride bytes (40 fp16)
    constexpr int TBB  = 128 * RSTB;         // 10240 B per operand per stage

    extern __shared__ __align__(16) uint32_t sm[];
    const uint32_t sA = smem_u32(sm);
    const uint32_t sB = sA + 4 * TBB;

    const uint32_t* Bt = (const uint32_t*)Bt16;
    const int Ku = K / 2;

    const int tid  = threadIdx.x;
    const int wid  = tid >> 5;
    const int lane = tid & 31;
    const int qr   = lane >> 2;
    const int qc   = lane & 3;
    const int wm   = wid >> 1;
    const int wn   = wid & 1;

    const int row0 = blockIdx.y * 128;
    const int col0 = blockIdx.x * 128;

    const int lr = tid >> 1, lh = (tid & 1) * 8;
    const uint32_t* aS0 = A  + (size_t)(row0 + lr) * Ku + lh;
    const uint32_t* bS0 = Bt + (size_t)(col0 + lr) * Ku + lh;
    const uint32_t aD0 = sA + lr * RSTB + lh * 4;
    const uint32_t bD0 = sB + lr * RSTB + lh * 4;

    const int a_row = (lane & 7) + ((lane >> 3) & 1) * 8;
    const int a_ko  = (lane >> 4) * 16;
    const int b_row = (lane & 7) + (lane >> 4) * 8;
    const int b_ko  = ((lane >> 3) & 1) * 16;

    float acc[2][8][4] = {};
    const int NK = K / 32;

    auto load_tile = [&](int kt, int s) {
        const uint32_t* as = aS0 + kt * 16;
        const uint32_t* bs = bS0 + kt * 16;
        const uint32_t ad = aD0 + s * TBB;
        const uint32_t bd = bD0 + s * TBB;
        CP16(ad,      as);
        CP16(ad + 16, as + 4);
        CP16(bd,      bs);
        CP16(bd + 16, bs + 4);
        CP_COMMIT();
    };

    load_tile(0, 0);
    load_tile(1, 1);
    load_tile(2, 2);

    for (int kt = 0; kt < NK; kt++) {
        if (kt + 3 <= NK)      { CP_WAIT(2); }
        else if (kt + 2 == NK) { CP_WAIT(1); }
        else                   { CP_WAIT(0); }
        __syncthreads();
        if (kt + 3 < NK) load_tile(kt + 3, (kt + 3) & 3);

        const int cur = kt & 3;
        const uint32_t ab = sA + cur * TBB;
        const uint32_t bb = sB + cur * TBB;
        #pragma unroll
        for (int ks = 0; ks < 2; ks++) {
            uint32_t af[2][4], bf[8][2];
            #pragma unroll
            for (int mt = 0; mt < 2; mt++)
                LDSM4(af[mt][0], af[mt][1], af[mt][2], af[mt][3],
                      ab + (wm * 32 + mt * 16 + a_row) * RSTB + a_ko + ks * 32);
            #pragma unroll
            for (int np = 0; np < 4; np++)
                LDSM4(bf[np * 2][0], bf[np * 2][1], bf[np * 2 + 1][0], bf[np * 2 + 1][1],
                      bb + (wn * 64 + np * 16 + b_row) * RSTB + b_ko + ks * 32);
            #pragma unroll
            for (int mt = 0; mt < 2; mt++)
                #pragma unroll
                for (int nt = 0; nt < 8; nt++)
                    mma_f16(acc[mt][nt], af[mt], bf[nt][0], bf[nt][1]);
        }
    }

    // epilogue
    #pragma unroll
    for (int mt = 0; mt < 2; mt++) {
        const int r = row0 + wm * 32 + mt * 16 + qr;
        #pragma unroll
        for (int nt = 0; nt < 8; nt++) {
            const int c = col0 + wn * 64 + nt * 8 + 2 * qc;
            const float bz0 = bias[c], bz1 = bias[c + 1];
            const float v00 = acc[mt][nt][0] + bz0;
            const float v01 = acc[mt][nt][1] + bz1;
            const float v10 = acc[mt][nt][2] + bz0;
            const float v11 = acc[mt][nt][3] + bz1;
            if (MODE == 0) {
                *(float2*)&C[(size_t)r * N + c]       = make_float2(v00, v01);
                *(float2*)&C[(size_t)(r + 8) * N + c] = make_float2(v10, v11);
            } else {
                const int sec = c >> 10, cc = c & 1023;
                const int h = cc >> 6, d = cc & 63;
                const int b = r >> 11, t = r & 2047;
                const float sc = (sec == 1) ? KSCALE : 1.0f;
                uint32_t* dst = (sec == 0 ? g_Q16 : sec == 1 ? g_K16 : g_Vh);
                const size_t off = (((size_t)(b * N_HEADS + h) * SEQ + t) * HEAD_DIM + d) >> 1;
                dst[off]       = packh2(v00 * sc, v01 * sc);
                dst[off + 256] = packh2(v10 * sc, v11 * sc);   // +8 rows
            }
        }
    }
}

// ---------------------------------------------------------------------------
// FP16 flash attention, causal.  128 q rows, 4 warps x 32 rows, 2 CTAs/SM.
// S = QK^T fp16 k16.  P in registers via packed ex2.f16x2.  Row-sum l via
// tensor core (all-ones B).  Per-warp causal tile skip (compute only).
// Double-buffered K/V cp.async, heavy q-tiles first.
// ---------------------------------------------------------------------------
__global__ __launch_bounds__(128, 2)
void flash_tc_kernel()
{
    constexpr int ROWB = 144;            // row stride bytes (72 fp16)
    constexpr int TILB = 64 * ROWB;      // 9216 B per buffer

    extern __shared__ __align__(16) char smemc[];
    const uint32_t sK = smem_u32(smemc);
    const uint32_t sV = sK + 2 * TILB;

    const int bh   = blockIdx.y;
    const int qx   = gridDim.x - 1 - blockIdx.x;       // heavy tiles first
    const int tid  = threadIdx.x;
    const int wid  = tid >> 5;                         // 0..3
    const int lane = tid & 31;
    const int qr   = lane >> 2;
    const int qc   = lane & 3;

    const uint32_t* Qb = g_Q16 + (size_t)bh * SEQ * (HEAD_DIM / 2);
    const uint32_t* Kb = g_K16 + (size_t)bh * SEQ * (HEAD_DIM / 2);
    const uint32_t* Vb = g_Vh  + (size_t)bh * SEQ * (HEAD_DIM / 2);

    const int rowbase = qx * 128 + wid * 32;
    const int lastTile    = (rowbase + 31) >> 6;       // last tile this warp needs
    const int firstMasked = (rowbase + 1) >> 6;        // first tile needing mask

    // persistent Q fragments: 2 m16 sub-tiles x 4 k16 chunks
    uint32_t qf[2][4][4];
    #pragma unroll
    for (int mt = 0; mt < 2; mt++) {
        const uint32_t* r0 = Qb + (size_t)(rowbase + mt * 16 + qr) * (HEAD_DIM / 2);
        const uint32_t* r1 = r0 + 8 * (HEAD_DIM / 2);
        #pragma unroll
        for (int kc = 0; kc < 4; kc++) {
            qf[mt][kc][0] = r0[kc * 8 + qc];
            qf[mt][kc][1] = r1[kc * 8 + qc];
            qf[mt][kc][2] = r0[kc * 8 + qc + 4];
            qf[mt][kc][3] = r1[kc * 8 + qc + 4];
        }
    }

    float oacc[2][8][4] = {};
    float lacc[2][4] = {};
    float mm[2][2] = {{-1e30f, -1e30f}, {-1e30f, -1e30f}};

    const int nkt = 2 * (qx + 1);

    // loader coords
    const int ldrow  = tid >> 1;
    const int ldhalf = tid & 1;

    // ldmatrix lane addressing
    const int kb_row = (lane & 7) + (lane >> 4) * 8;        // K B-frags (+np*16)
    const int kb_ko  = ((lane >> 3) & 1) * 16;
    const int v_key  = (lane & 7) + ((lane >> 3) & 1) * 8;  // V trans frags
    const int v_d    = ((lane >> 4) & 1) * 8;

    auto load_tile = [&](int kt, int buf) {
        const uint32_t kD = sK + buf * TILB + ldrow * ROWB + ldhalf * 64;
        const uint32_t vD = sV + buf * TILB + ldrow * ROWB + ldhalf * 64;
        const uint32_t* kS = Kb + (size_t)(kt * 64 + ldrow) * 32 + ldhalf * 16;
        const uint32_t* vS = Vb + (size_t)(kt * 64 + ldrow) * 32 + ldhalf * 16;
        #pragma unroll
        for (int i = 0; i < 4; i++) {
            CP16(kD + i * 16, kS + i * 4);
            CP16(vD + i * 16, vS + i * 4);
        }
        CP_COMMIT();
    };

    load_tile(0, 0);

    for (int kt = 0; kt < nkt; kt++) {
        const int cur = kt & 1;
        const int kb = kt * 64;

        CP_WAIT(0);
        __syncthreads();
        if (kt + 1 < nkt) load_tile(kt + 1, cur ^ 1);

        if (kt > lastTile) continue;           // warp-uniform causal skip

        const uint32_t kbuf = sK + cur * TILB;
        const uint32_t vbuf = sV + cur * TILB;

        // ---- S = Q K^T (fp16 k16) ----
        float sa[2][8][4];
        #pragma unroll
        for (int mt = 0; mt < 2; mt++)
            #pragma unroll
            for (int nt = 0; nt < 8; nt++) {
                sa[mt][nt][0] = 0.f; sa[mt][nt][1] = 0.f;
                sa[mt][nt][2] = 0.f; sa[mt][nt][3] = 0.f;
            }
        #pragma unroll
        for (int kc = 0; kc < 4; kc++) {
            #pragma unroll
            for (int np = 0; np < 4; np++) {
                uint32_t r0, r1, r2, r3;
                LDSM4(r0, r1, r2, r3,
                      kbuf + (np * 16 + kb_row) * ROWB + kb_ko + kc * 32);
                mma_f16(sa[0][np * 2],     qf[0][kc], r0, r1);
                mma_f16(sa[0][np * 2 + 1], qf[0][kc], r2, r3);
                mma_f16(sa[1][np * 2],     qf[1][kc], r0, r1);
                mma_f16(sa[1][np * 2 + 1], qf[1][kc], r2, r3);
            }
        }

        // ---- mask + online softmax; P via packed f16x2 ex2 ----
        uint32_t ph[2][8][2];
        #pragma unroll
        for (int mt = 0; mt < 2; mt++) {
            if (kt >= firstMasked) {
                const int r0g = rowbase + mt * 16 + qr;
                const int r1g = r0g + 8;
                #pragma unroll
                for (int nt = 0; nt < 8; nt++) {
                    const int cg = kb + nt * 8 + 2 * qc;
                    if (cg     > r0g) sa[mt][nt][0] = -1e30f;
                    if (cg + 1 > r0g) sa[mt][nt][1] = -1e30f;
                    if (cg     > r1g) sa[mt][nt][2] = -1e30f;
                    if (cg + 1 > r1g) sa[mt][nt][3] = -1e30f;
                }
            }

            float t0 = -1e30f, t1 = -1e30f;
            #pragma unroll
            for (int nt = 0; nt < 8; nt++) {
                t0 = fmaxf(t0, fmaxf(sa[mt][nt][0], sa[mt][nt][1]));
                t1 = fmaxf(t1, fmaxf(sa[mt][nt][2], sa[mt][nt][3]));
            }
            t0 = fmaxf(t0, __shfl_xor_sync(0xffffffffu, t0, 1));
            t0 = fmaxf(t0, __shfl_xor_sync(0xffffffffu, t0, 2));
            t1 = fmaxf(t1, __shfl_xor_sync(0xffffffffu, t1, 1));
            t1 = fmaxf(t1, __shfl_xor_sync(0xffffffffu, t1, 2));

            const float mn0 = fmaxf(mm[mt][0], t0);
            const float mn1 = fmaxf(mm[mt][1], t1);
            const float c0 = ex2(mm[mt][0] - mn0);
            const float c1 = ex2(mm[mt][1] - mn1);
            lacc[mt][0] *= c0; lacc[mt][1] *= c0;
            lacc[mt][2] *= c1; lacc[mt][3] *= c1;
            #pragma unroll
            for (int nt = 0; nt < 8; nt++) {
                oacc[mt][nt][0] *= c0; oacc[mt][nt][1] *= c0;
                oacc[mt][nt][2] *= c1; oacc[mt][nt][3] *= c1;
            }

            #pragma unroll
            for (int nt = 0; nt < 8; nt++) {
                ph[mt][nt][0] = h2ex2(packh2(sa[mt][nt][0] - mn0,
                                             sa[mt][nt][1] - mn0));
                ph[mt][nt][1] = h2ex2(packh2(sa[mt][nt][2] - mn1,
                                             sa[mt][nt][3] - mn1));
            }
            mm[mt][0] = mn0; mm[mt][1] = mn1;
        }

        // ---- O += P V ; l += P·1  (fp16 k16; P from registers) ----
        #pragma unroll
        for (int j = 0; j < 4; j++) {
            uint32_t pa0[4], pa1[4];
            pa0[0] = ph[0][2 * j][0];     pa0[1] = ph[0][2 * j][1];
            pa0[2] = ph[0][2 * j + 1][0]; pa0[3] = ph[0][2 * j + 1][1];
            pa1[0] = ph[1][2 * j][0];     pa1[1] = ph[1][2 * j][1];
            pa1[2] = ph[1][2 * j + 1][0]; pa1[3] = ph[1][2 * j + 1][1];
            #pragma unroll
            for (int db = 0; db < 4; db++) {
                uint32_t r0, r1, r2, r3;
                const uint32_t addr = vbuf + (j * 16 + v_key) * ROWB
                                    + (db * 16 + v_d) * 2;
                LDSM4T(r0, r1, r2, r3, addr);
                mma_f16(oacc[0][db * 2],     pa0, r0, r1);
                mma_f16(oacc[0][db * 2 + 1], pa0, r2, r3);
                mma_f16(oacc[1][db * 2],     pa1, r0, r1);
                mma_f16(oacc[1][db * 2 + 1], pa1, r2, r3);
            }
            mma_f16(lacc[0], pa0, ONESH2, ONESH2);
            mma_f16(lacc[1], pa1, ONESH2, ONESH2);
        }
    }

    // ---- epilogue: normalize, write fp16 to g_AO16 [B*T][C] ----
    const int b = bh >> 4;
    const int h = bh & 15;
    #pragma unroll
    for (int mt = 0; mt < 2; mt++) {
        const float inv0 = 1.f / lacc[mt][0];
        const float inv1 = 1.f / lacc[mt][2];
        const int t0g = rowbase + mt * 16 + qr;
        uint32_t* o0 = g_AO16 + ((size_t)(b * SEQ + t0g)) * (D_MODEL / 2) + h * 32;
        uint32_t* o1 = o0 + 8 * (D_MODEL / 2);
        #pragma unroll
        for (int nt = 0; nt < 8; nt++) {
            o0[nt * 4 + qc] = packh2(oacc[mt][nt][0] * inv0, oacc[mt][nt][1] * inv0);
            o1[nt * 4 + qc] = packh2(oacc[mt][nt][2] * inv1, oacc[mt][nt][3] * inv1);
        }
    }
}

// ---------------------------------------------------------------------------
extern "C" void kernel_launch(void* const* d_in, const int* in_sizes, int n_in,
                              void* d_out, int out_size)
{
    const float* x     = (const float*)d_in[0];
    const float* W_qkv = (const float*)d_in[1];
    const float* b_qkv = (const float*)d_in[2];
    const float* W_out = (const float*)d_in[3];
    const float* b_out = (const float*)d_in[4];
    float* out = (float*)d_out;

    const int gemm_smem  = 8 * 10240;          // 81920 (4 stages x A+B)
    const int flash_smem = 4 * 9216;           // 36864
    cudaFuncSetAttribute(hgemm<0>, cudaFuncAttributeMaxDynamicSharedMemorySize, gemm_smem);
    cudaFuncSetAttribute(hgemm<1>, cudaFuncAttributeMaxDynamicSharedMemorySize, gemm_smem);
    cudaFuncSetAttribute(flash_tc_kernel, cudaFuncAttributeMaxDynamicSharedMemorySize, flash_smem);

    uint32_t *x16, *ao;
    uint16_t *w1t, *w2t;
    cudaGetSymbolAddress((void**)&x16, g_x16);
    cudaGetSymbolAddress((void**)&w1t, g_w1t16);
    cudaGetSymbolAddress((void**)&w2t, g_w2t16);
    cudaGetSymbolAddress((void**)&ao,  g_AO16);

    // 0) pre-convert: x -> fp16; weights -> transposed [N][K] fp16
    {
        int n4 = MROWS * D_MODEL / 4;
        cvt_f16_kernel<<<(n4 + 255) / 256, 256>>>((const float4*)x, (uint2*)x16, n4);
        cvt_transpose_f16<<<dim3(QKV_N / 32, D_MODEL / 32), dim3(32, 8)>>>(
            W_qkv, w1t, D_MODEL, QKV_N);
        cvt_transpose_f16<<<dim3(D_MODEL / 32, D_MODEL / 32), dim3(32, 8)>>>(
            W_out, w2t, D_MODEL, D_MODEL);
    }
    // 1) QKV projection -> g_Q16 / g_K16 (scaled) / g_Vh (all fp16)
    {
        dim3 grid(QKV_N / 128, MROWS / 128);    // (24, 64)
        hgemm<1><<<grid, 256, gemm_smem>>>(x16, w1t, b_qkv, nullptr,
                                           MROWS, QKV_N, D_MODEL);
    }
    // 2) causal flash attention -> g_AO16 (fp16)
    {
        dim3 grid(SEQ / 128, BATCH * N_HEADS);  // (16, 64)
        flash_tc_kernel<<<grid, 128, flash_smem>>>();
    }
    // 3) output projection -> d_out (fp32)
    {
        dim3 grid(D_MODEL / 128, MROWS / 128);  // (8, 64)
        hgemm<0><<<grid, 256, gemm_smem>>>(ao, w2t, b_out, out,
                                           MROWS, D_MODEL, D_MODEL);
    }
}

// round 15
// speedup vs baseline: 1.1578x; 1.0093x over previous
#include <cuda_runtime.h>
#include <math.h>
#include <stdint.h>

#define D_MODEL 1024
#define N_HEADS 16
#define HEAD_DIM 64
#define BATCH 4
#define SEQ 2048
#define MROWS (BATCH * SEQ)          // 8192
#define QKV_N (3 * D_MODEL)          // 3072

// softmax scale folded into K at QKV epilogue: 1/sqrt(64) * log2(e)
#define KSCALE 0.18033688011111793f
#define ONESH2 0x3C003C00u          // f16x2 {1.0, 1.0}

// ---------------- scratch (__device__ globals), all fp16 payloads ----------
__device__ __align__(16) uint32_t g_Q16[BATCH * N_HEADS * SEQ * HEAD_DIM / 2];
__device__ __align__(16) uint32_t g_K16[BATCH * N_HEADS * SEQ * HEAD_DIM / 2];
__device__ __align__(16) uint32_t g_Vh [BATCH * N_HEADS * SEQ * HEAD_DIM / 2];
__device__ __align__(16) uint32_t g_AO16[MROWS * D_MODEL / 2];
__device__ __align__(16) uint32_t g_x16 [MROWS * D_MODEL / 2];
__device__ __align__(16) uint16_t g_w1t16[QKV_N * D_MODEL];    // [N][K] fp16
__device__ __align__(16) uint16_t g_w2t16[D_MODEL * D_MODEL];  // [N][K] fp16

// ---------------- helpers ----------------------------------------------------
__device__ __forceinline__ uint32_t smem_u32(const void* p) {
    uint32_t a;
    asm("{ .reg .u64 t; cvta.to.shared.u64 t, %1; cvt.u32.u64 %0, t; }"
        : "=r"(a) : "l"(p));
    return a;
}
__device__ __forceinline__ float ex2(float x) {
    float r; asm("ex2.approx.f32 %0, %1;" : "=f"(r) : "f"(x)); return r;
}
__device__ __forceinline__ uint32_t h2ex2(uint32_t x) {
    uint32_t r; asm("ex2.approx.f16x2 %0, %1;" : "=r"(r) : "r"(x)); return r;
}
// pack two fp32 -> f16x2 (lo = first arg)
__device__ __forceinline__ uint32_t packh2(float lo, float hi) {
    uint32_t u;
    asm("cvt.rn.f16x2.f32 %0, %1, %2;" : "=r"(u) : "f"(hi), "f"(lo));
    return u;
}
__device__ __forceinline__ uint16_t f2h(float f) {
    uint16_t u; asm("cvt.rn.f16.f32 %0, %1;" : "=h"(u) : "f"(f)); return u;
}
__device__ __forceinline__ void mma_f16(float* d, const uint32_t* a,
                                        uint32_t b0, uint32_t b1) {
    asm volatile(
        "mma.sync.aligned.m16n8k16.row.col.f32.f16.f16.f32 "
        "{%0,%1,%2,%3}, {%4,%5,%6,%7}, {%8,%9}, {%0,%1,%2,%3};\n"
        : "+f"(d[0]), "+f"(d[1]), "+f"(d[2]), "+f"(d[3])
        : "r"(a[0]), "r"(a[1]), "r"(a[2]), "r"(a[3]), "r"(b0), "r"(b1));
}
#define LDSM4(r0, r1, r2, r3, addr) \
    asm volatile("ldmatrix.sync.aligned.m8n8.x4.shared.b16 {%0,%1,%2,%3}, [%4];" \
                 : "=r"(r0), "=r"(r1), "=r"(r2), "=r"(r3) : "r"(addr))
#define LDSM4T(r0, r1, r2, r3, addr) \
    asm volatile("ldmatrix.sync.aligned.m8n8.x4.trans.shared.b16 {%0,%1,%2,%3}, [%4];" \
                 : "=r"(r0), "=r"(r1), "=r"(r2), "=r"(r3) : "r"(addr))
#define CP16(dst, src) \
    asm volatile("cp.async.cg.shared.global [%0], [%1], 16;" :: "r"(dst), "l"(src))
#define CP_COMMIT() asm volatile("cp.async.commit_group;")
#define CP_WAIT(n)  asm volatile("cp.async.wait_group %0;" :: "n"(n))

// ---------------------------------------------------------------------------
// Elementwise fp32 -> fp16x2
// ---------------------------------------------------------------------------
__global__ __launch_bounds__(256)
void cvt_f16_kernel(const float4* __restrict__ src, uint2* __restrict__ dst, int n4)
{
    int i = blockIdx.x * blockDim.x + threadIdx.x;
    if (i >= n4) return;
    float4 v = src[i];
    dst[i] = make_uint2(packh2(v.x, v.y), packh2(v.z, v.w));
}

// Transpose + convert BOTH weight matrices in one launch.
// blocks x < 96: W_qkv [1024][3072] -> g_w1t16; else W_out -> g_w2t16.
__global__ __launch_bounds__(256)
void cvt_transpose_both(const float* __restrict__ W1, const float* __restrict__ W2,
                        uint16_t* __restrict__ T1, uint16_t* __restrict__ T2)
{
    __shared__ float tile[32][33];
    const int bx = blockIdx.x;
    const float* W; uint16_t* T; int N, n0;
    if (bx < QKV_N / 32) { W = W1; T = T1; N = QKV_N; n0 = bx * 32; }
    else                 { W = W2; T = T2; N = D_MODEL; n0 = (bx - QKV_N / 32) * 32; }
    const int K = D_MODEL;
    const int k0 = blockIdx.y * 32;
    const int tx = threadIdx.x, ty = threadIdx.y;     // 32 x 8
    #pragma unroll
    for (int i = 0; i < 32; i += 8)
        tile[ty + i][tx] = W[(size_t)(k0 + ty + i) * N + n0 + tx];
    __syncthreads();
    #pragma unroll
    for (int i = 0; i < 32; i += 8)
        T[(size_t)(n0 + ty + i) * K + k0 + tx] = f2h(tile[tx][ty + i]);
}

// ---------------------------------------------------------------------------
// FP16 GEMM (unchanged from round 14): 128x128 CTA tile, BK=32, 8 warps
// (4Mx2N, warp 32x64), 4-stage cp.async ring, ldmatrix fragments.
// ---------------------------------------------------------------------------
template <int MODE>
__global__ __launch_bounds__(256, 2)
void hgemm(const uint32_t* __restrict__ A, const uint16_t* __restrict__ Bt16,
           const float* __restrict__ bias, float* __restrict__ C,
           int M, int N, int K)
{
    constexpr int RSTB = 80;                 // row stride bytes (40 fp16)
    constexpr int TBB  = 128 * RSTB;         // 10240 B per operand per stage

    extern __shared__ __align__(16) uint32_t sm[];
    const uint32_t sA = smem_u32(sm);
    const uint32_t sB = sA + 4 * TBB;

    const uint32_t* Bt = (const uint32_t*)Bt16;
    const int Ku = K / 2;

    const int tid  = threadIdx.x;
    const int wid  = tid >> 5;
    const int lane = tid & 31;
    const int qr   = lane >> 2;
    const int qc   = lane & 3;
    const int wm   = wid >> 1;
    const int wn   = wid & 1;

    const int row0 = blockIdx.y * 128;
    const int col0 = blockIdx.x * 128;

    const int lr = tid >> 1, lh = (tid & 1) * 8;
    const uint32_t* aS0 = A  + (size_t)(row0 + lr) * Ku + lh;
    const uint32_t* bS0 = Bt + (size_t)(col0 + lr) * Ku + lh;
    const uint32_t aD0 = sA + lr * RSTB + lh * 4;
    const uint32_t bD0 = sB + lr * RSTB + lh * 4;

    const int a_row = (lane & 7) + ((lane >> 3) & 1) * 8;
    const int a_ko  = (lane >> 4) * 16;
    const int b_row = (lane & 7) + (lane >> 4) * 8;
    const int b_ko  = ((lane >> 3) & 1) * 16;

    float acc[2][8][4] = {};
    const int NK = K / 32;

    auto load_tile = [&](int kt, int s) {
        const uint32_t* as = aS0 + kt * 16;
        const uint32_t* bs = bS0 + kt * 16;
        const uint32_t ad = aD0 + s * TBB;
        const uint32_t bd = bD0 + s * TBB;
        CP16(ad,      as);
        CP16(ad + 16, as + 4);
        CP16(bd,      bs);
        CP16(bd + 16, bs + 4);
        CP_COMMIT();
    };

    load_tile(0, 0);
    load_tile(1, 1);
    load_tile(2, 2);

    for (int kt = 0; kt < NK; kt++) {
        if (kt + 3 <= NK)      { CP_WAIT(2); }
        else if (kt + 2 == NK) { CP_WAIT(1); }
        else                   { CP_WAIT(0); }
        __syncthreads();
        if (kt + 3 < NK) load_tile(kt + 3, (kt + 3) & 3);

        const int cur = kt & 3;
        const uint32_t ab = sA + cur * TBB;
        const uint32_t bb = sB + cur * TBB;
        #pragma unroll
        for (int ks = 0; ks < 2; ks++) {
            uint32_t af[2][4], bf[8][2];
            #pragma unroll
            for (int mt = 0; mt < 2; mt++)
                LDSM4(af[mt][0], af[mt][1], af[mt][2], af[mt][3],
                      ab + (wm * 32 + mt * 16 + a_row) * RSTB + a_ko + ks * 32);
            #pragma unroll
            for (int np = 0; np < 4; np++)
                LDSM4(bf[np * 2][0], bf[np * 2][1], bf[np * 2 + 1][0], bf[np * 2 + 1][1],
                      bb + (wn * 64 + np * 16 + b_row) * RSTB + b_ko + ks * 32);
            #pragma unroll
            for (int mt = 0; mt < 2; mt++)
                #pragma unroll
                for (int nt = 0; nt < 8; nt++)
                    mma_f16(acc[mt][nt], af[mt], bf[nt][0], bf[nt][1]);
        }
    }

    // epilogue
    #pragma unroll
    for (int mt = 0; mt < 2; mt++) {
        const int r = row0 + wm * 32 + mt * 16 + qr;
        #pragma unroll
        for (int nt = 0; nt < 8; nt++) {
            const int c = col0 + wn * 64 + nt * 8 + 2 * qc;
            const float bz0 = bias[c], bz1 = bias[c + 1];
            const float v00 = acc[mt][nt][0] + bz0;
            const float v01 = acc[mt][nt][1] + bz1;
            const float v10 = acc[mt][nt][2] + bz0;
            const float v11 = acc[mt][nt][3] + bz1;
            if (MODE == 0) {
                *(float2*)&C[(size_t)r * N + c]       = make_float2(v00, v01);
                *(float2*)&C[(size_t)(r + 8) * N + c] = make_float2(v10, v11);
            } else {
                const int sec = c >> 10, cc = c & 1023;
                const int h = cc >> 6, d = cc & 63;
                const int b = r >> 11, t = r & 2047;
                const float sc = (sec == 1) ? KSCALE : 1.0f;
                uint32_t* dst = (sec == 0 ? g_Q16 : sec == 1 ? g_K16 : g_Vh);
                const size_t off = (((size_t)(b * N_HEADS + h) * SEQ + t) * HEAD_DIM + d) >> 1;
                dst[off]       = packh2(v00 * sc, v01 * sc);
                dst[off + 256] = packh2(v10 * sc, v11 * sc);   // +8 rows
            }
        }
    }
}

// ---------------------------------------------------------------------------
// FP16 flash attention, causal.  128 q rows, 4 warps x 32 rows, KT=32 keys,
// 3 CTAs/SM (sa shrunk to 32 regs -> no spills at the 170-reg cap).
// S = QK^T fp16 k16.  P in registers via packed ex2.f16x2.  Row-sum l via
// tensor core (all-ones B).  Exactly one masked (diagonal) tile per warp;
// up to 3 fully-masked tiles skipped per warp.  Double-buffered K/V.
// ---------------------------------------------------------------------------
__global__ __launch_bounds__(128, 3)
void flash_tc_kernel()
{
    constexpr int ROWB = 144;            // row stride bytes (72 fp16)
    constexpr int TILB = 32 * ROWB;      // 4608 B per buffer (32 keys)

    extern __shared__ __align__(16) char smemc[];
    const uint32_t sK = smem_u32(smemc);
    const uint32_t sV = sK + 2 * TILB;

    const int bh   = blockIdx.y;
    const int qx   = gridDim.x - 1 - blockIdx.x;       // heavy tiles first
    const int tid  = threadIdx.x;
    const int wid  = tid >> 5;                         // 0..3
    const int lane = tid & 31;
    const int qr   = lane >> 2;
    const int qc   = lane & 3;

    const uint32_t* Qb = g_Q16 + (size_t)bh * SEQ * (HEAD_DIM / 2);
    const uint32_t* Kb = g_K16 + (size_t)bh * SEQ * (HEAD_DIM / 2);
    const uint32_t* Vb = g_Vh  + (size_t)bh * SEQ * (HEAD_DIM / 2);

    const int rowbase  = qx * 128 + wid * 32;
    const int diagTile = rowbase >> 5;     // only tile needing mask; also last

    // persistent Q fragments: 2 m16 sub-tiles x 4 k16 chunks
    uint32_t qf[2][4][4];
    #pragma unroll
    for (int mt = 0; mt < 2; mt++) {
        const uint32_t* r0 = Qb + (size_t)(rowbase + mt * 16 + qr) * (HEAD_DIM / 2);
        const uint32_t* r1 = r0 + 8 * (HEAD_DIM / 2);
        #pragma unroll
        for (int kc = 0; kc < 4; kc++) {
            qf[mt][kc][0] = r0[kc * 8 + qc];
            qf[mt][kc][1] = r1[kc * 8 + qc];
            qf[mt][kc][2] = r0[kc * 8 + qc + 4];
            qf[mt][kc][3] = r1[kc * 8 + qc + 4];
        }
    }

    float oacc[2][8][4] = {};
    float lacc[2][4] = {};
    float mm[2][2] = {{-1e30f, -1e30f}, {-1e30f, -1e30f}};

    const int nkt = 4 * (qx + 1);          // 32-key tiles

    // loader coords: row = tid>>2 (0..31), quarter = tid&3 owns 32B of 128B
    const int ldrow = tid >> 2;
    const int ldq   = (tid & 3) * 8;       // u32 offset

    // ldmatrix lane addressing
    const int kb_row = (lane & 7) + (lane >> 4) * 8;        // K B-frags (+np*16)
    const int kb_ko  = ((lane >> 3) & 1) * 16;
    const int v_key  = (lane & 7) + ((lane >> 3) & 1) * 8;  // V trans frags
    const int v_d    = ((lane >> 4) & 1) * 8;

    auto load_tile = [&](int kt, int buf) {
        const uint32_t kD = sK + buf * TILB + ldrow * ROWB + ldq * 4;
        const uint32_t vD = sV + buf * TILB + ldrow * ROWB + ldq * 4;
        const uint32_t* kS = Kb + (size_t)(kt * 32 + ldrow) * 32 + ldq;
        const uint32_t* vS = Vb + (size_t)(kt * 32 + ldrow) * 32 + ldq;
        CP16(kD,      kS);
        CP16(kD + 16, kS + 4);
        CP16(vD,      vS);
        CP16(vD + 16, vS + 4);
        CP_COMMIT();
    };

    load_tile(0, 0);

    for (int kt = 0; kt < nkt; kt++) {
        const int cur = kt & 1;
        const int kb = kt * 32;

        CP_WAIT(0);
        __syncthreads();
        if (kt + 1 < nkt) load_tile(kt + 1, cur ^ 1);

        if (kt > diagTile) continue;       // warp-uniform causal skip

        const uint32_t kbuf = sK + cur * TILB;
        const uint32_t vbuf = sV + cur * TILB;

        // ---- S = Q K^T (fp16 k16), 32 keys = 4 n8 tiles ----
        float sa[2][4][4];
        #pragma unroll
        for (int mt = 0; mt < 2; mt++)
            #pragma unroll
            for (int nt = 0; nt < 4; nt++) {
                sa[mt][nt][0] = 0.f; sa[mt][nt][1] = 0.f;
                sa[mt][nt][2] = 0.f; sa[mt][nt][3] = 0.f;
            }
        #pragma unroll
        for (int kc = 0; kc < 4; kc++) {
            #pragma unroll
            for (int np = 0; np < 2; np++) {
                uint32_t r0, r1, r2, r3;
                LDSM4(r0, r1, r2, r3,
                      kbuf + (np * 16 + kb_row) * ROWB + kb_ko + kc * 32);
                mma_f16(sa[0][np * 2],     qf[0][kc], r0, r1);
                mma_f16(sa[0][np * 2 + 1], qf[0][kc], r2, r3);
                mma_f16(sa[1][np * 2],     qf[1][kc], r0, r1);
                mma_f16(sa[1][np * 2 + 1], qf[1][kc], r2, r3);
            }
        }

        // ---- mask + online softmax; P via packed f16x2 ex2 ----
        uint32_t ph[2][4][2];
        const bool needMask = (kt == diagTile);
        #pragma unroll
        for (int mt = 0; mt < 2; mt++) {
            if (needMask) {
                const int r0g = rowbase + mt * 16 + qr;
                const int r1g = r0g + 8;
                #pragma unroll
                for (int nt = 0; nt < 4; nt++) {
                    const int cg = kb + nt * 8 + 2 * qc;
                    if (cg     > r0g) sa[mt][nt][0] = -1e30f;
                    if (cg + 1 > r0g) sa[mt][nt][1] = -1e30f;
                    if (cg     > r1g) sa[mt][nt][2] = -1e30f;
                    if (cg + 1 > r1g) sa[mt][nt][3] = -1e30f;
                }
            }

            float t0 = -1e30f, t1 = -1e30f;
            #pragma unroll
            for (int nt = 0; nt < 4; nt++) {
                t0 = fmaxf(t0, fmaxf(sa[mt][nt][0], sa[mt][nt][1]));
                t1 = fmaxf(t1, fmaxf(sa[mt][nt][2], sa[mt][nt][3]));
            }
            t0 = fmaxf(t0, __shfl_xor_sync(0xffffffffu, t0, 1));
            t0 = fmaxf(t0, __shfl_xor_sync(0xffffffffu, t0, 2));
            t1 = fmaxf(t1, __shfl_xor_sync(0xffffffffu, t1, 1));
            t1 = fmaxf(t1, __shfl_xor_sync(0xffffffffu, t1, 2));

            const float mn0 = fmaxf(mm[mt][0], t0);
            const float mn1 = fmaxf(mm[mt][1], t1);
            const float c0 = ex2(mm[mt][0] - mn0);
            const float c1 = ex2(mm[mt][1] - mn1);
            lacc[mt][0] *= c0; lacc[mt][1] *= c0;
            lacc[mt][2] *= c1; lacc[mt][3] *= c1;
            #pragma unroll
            for (int nt = 0; nt < 8; nt++) {
                oacc[mt][nt][0] *= c0; oacc[mt][nt][1] *= c0;
                oacc[mt][nt][2] *= c1; oacc[mt][nt][3] *= c1;
            }

            #pragma unroll
            for (int nt = 0; nt < 4; nt++) {
                ph[mt][nt][0] = h2ex2(packh2(sa[mt][nt][0] - mn0,
                                             sa[mt][nt][1] - mn0));
                ph[mt][nt][1] = h2ex2(packh2(sa[mt][nt][2] - mn1,
                                             sa[mt][nt][3] - mn1));
            }
            mm[mt][0] = mn0; mm[mt][1] = mn1;
        }

        // ---- O += P V ; l += P·1  (fp16 k16; P from registers) ----
        #pragma unroll
        for (int j = 0; j < 2; j++) {                 // k16 chunk (keys 16j..)
            uint32_t pa0[4], pa1[4];
            pa0[0] = ph[0][2 * j][0];     pa0[1] = ph[0][2 * j][1];
            pa0[2] = ph[0][2 * j + 1][0]; pa0[3] = ph[0][2 * j + 1][1];
            pa1[0] = ph[1][2 * j][0];     pa1[1] = ph[1][2 * j][1];
            pa1[2] = ph[1][2 * j + 1][0]; pa1[3] = ph[1][2 * j + 1][1];
            #pragma unroll
            for (int db = 0; db < 4; db++) {
                uint32_t r0, r1, r2, r3;
                const uint32_t addr = vbuf + (j * 16 + v_key) * ROWB
                                    + (db * 16 + v_d) * 2;
                LDSM4T(r0, r1, r2, r3, addr);
                mma_f16(oacc[0][db * 2],     pa0, r0, r1);
                mma_f16(oacc[0][db * 2 + 1], pa0, r2, r3);
                mma_f16(oacc[1][db * 2],     pa1, r0, r1);
                mma_f16(oacc[1][db * 2 + 1], pa1, r2, r3);
            }
            mma_f16(lacc[0], pa0, ONESH2, ONESH2);
            mma_f16(lacc[1], pa1, ONESH2, ONESH2);
        }
    }

    // ---- epilogue: normalize, write fp16 to g_AO16 [B*T][C] ----
    const int b = bh >> 4;
    const int h = bh & 15;
    #pragma unroll
    for (int mt = 0; mt < 2; mt++) {
        const float inv0 = 1.f / lacc[mt][0];
        const float inv1 = 1.f / lacc[mt][2];
        const int t0g = rowbase + mt * 16 + qr;
        uint32_t* o0 = g_AO16 + ((size_t)(b * SEQ + t0g)) * (D_MODEL / 2) + h * 32;
        uint32_t* o1 = o0 + 8 * (D_MODEL / 2);
        #pragma unroll
        for (int nt = 0; nt < 8; nt++) {
            o0[nt * 4 + qc] = packh2(oacc[mt][nt][0] * inv0, oacc[mt][nt][1] * inv0);
            o1[nt * 4 + qc] = packh2(oacc[mt][nt][2] * inv1, oacc[mt][nt][3] * inv1);
        }
    }
}

// ---------------------------------------------------------------------------
extern "C" void kernel_launch(void* const* d_in, const int* in_sizes, int n_in,
                              void* d_out, int out_size)
{
    const float* x     = (const float*)d_in[0];
    const float* W_qkv = (const float*)d_in[1];
    const float* b_qkv = (const float*)d_in[2];
    const float* W_out = (const float*)d_in[3];
    const float* b_out = (const float*)d_in[4];
    float* out = (float*)d_out;

    const int gemm_smem  = 8 * 10240;          // 81920 (4 stages x A+B)
    const int flash_smem = 4 * 4608;           // 18432
    cudaFuncSetAttribute(hgemm<0>, cudaFuncAttributeMaxDynamicSharedMemorySize, gemm_smem);
    cudaFuncSetAttribute(hgemm<1>, cudaFuncAttributeMaxDynamicSharedMemorySize, gemm_smem);
    cudaFuncSetAttribute(flash_tc_kernel, cudaFuncAttributeMaxDynamicSharedMemorySize, flash_smem);

    uint32_t *x16, *ao;
    uint16_t *w1t, *w2t;
    cudaGetSymbolAddress((void**)&x16, g_x16);
    cudaGetSymbolAddress((void**)&w1t, g_w1t16);
    cudaGetSymbolAddress((void**)&w2t, g_w2t16);
    cudaGetSymbolAddress((void**)&ao,  g_AO16);

    // 0) pre-convert: x -> fp16; both weights -> transposed [N][K] fp16 (1 launch)
    {
        int n4 = MROWS * D_MODEL / 4;
        cvt_f16_kernel<<<(n4 + 255) / 256, 256>>>((const float4*)x, (uint2*)x16, n4);
        cvt_transpose_both<<<dim3((QKV_N + D_MODEL) / 32, D_MODEL / 32), dim3(32, 8)>>>(
            W_qkv, W_out, w1t, w2t);
    }
    // 1) QKV projection -> g_Q16 / g_K16 (scaled) / g_Vh (all fp16)
    {
        dim3 grid(QKV_N / 128, MROWS / 128);    // (24, 64)
        hgemm<1><<<grid, 256, gemm_smem>>>(x16, w1t, b_qkv, nullptr,
                                           MROWS, QKV_N, D_MODEL);
    }
    // 2) causal flash attention -> g_AO16 (fp16)
    {
        dim3 grid(SEQ / 128, BATCH * N_HEADS);  // (16, 64)
        flash_tc_kernel<<<grid, 128, flash_smem>>>();
    }
    // 3) output projection -> d_out (fp32)
    {
        dim3 grid(D_MODEL / 128, MROWS / 128);  // (8, 64)
        hgemm<0><<<grid, 256, gemm_smem>>>(ao, w2t, b_out, out,
                                           MROWS, D_MODEL, D_MODEL);
    }
}